// round 10
// baseline (speedup 1.0000x reference)
#include <cuda_runtime.h>
#include <cuda_bf16.h>
#include <cstdint>

#define HW 16384
#define PITCH 264
#define GEMM_SMEM ((256*PITCH + 128*PITCH)*2)   // Bs 256 rows + As 128 rows, bf16

// ---------------- scratch (device globals; no allocations allowed) ----------
__device__ __nv_bfloat16 g_qkvT[(size_t)8*HW*768];   // [bv][p][768] bf16
__device__ __nv_bfloat16 g_wqkv[768*256];
__device__ __nv_bfloat16 g_wproj[256*256];
__device__ float g_part[64][8][2];
__device__ float g_mean[64];
__device__ float g_rstd[64];

// ---------------- helpers ----------------------------------------------------
__device__ __forceinline__ uint32_t s2u(const void* p){
    return (uint32_t)__cvta_generic_to_shared(p);
}
__device__ __forceinline__ void ldsm4(uint32_t r[4], uint32_t addr){
    asm volatile("ldmatrix.sync.aligned.m8n8.x4.shared.b16 {%0,%1,%2,%3}, [%4];"
        : "=r"(r[0]), "=r"(r[1]), "=r"(r[2]), "=r"(r[3]) : "r"(addr));
}
__device__ __forceinline__ void mma_bf16(float c[4], const uint32_t a[4],
                                         uint32_t b0, uint32_t b1){
    asm volatile(
      "mma.sync.aligned.m16n8k16.row.col.f32.bf16.bf16.f32 "
      "{%0,%1,%2,%3},{%4,%5,%6,%7},{%8,%9},{%0,%1,%2,%3};\n"
      : "+f"(c[0]), "+f"(c[1]), "+f"(c[2]), "+f"(c[3])
      : "r"(a[0]), "r"(a[1]), "r"(a[2]), "r"(a[3]), "r"(b0), "r"(b1));
}

// load a [128 m][256 k] bf16 weight tile into smem [128][PITCH], 512 threads
__device__ __forceinline__ void load_w128(__nv_bfloat16* As,
                                          const __nv_bfloat16* W, int t){
    #pragma unroll
    for (int it = 0; it < 8; ++it){
        const int lin = it*512 + t;
        const int r = lin >> 5, k16 = lin & 31;
        *(uint4*)(As + r*PITCH + k16*8) = *(const uint4*)(W + r*256 + k16*8);
    }
}

// ---------------- weight convert ---------------------------------------------
__global__ void k_convert(const float* __restrict__ wq, const float* __restrict__ wp){
    int i = blockIdx.x*256 + threadIdx.x;
    if (i < 768*256) g_wqkv[i]  = __float2bfloat16(wq[i]);
    if (i < 256*256) g_wproj[i] = __float2bfloat16(wp[i]);
}

// ---------------- GroupNorm statistics ---------------------------------------
__global__ void k_stats(const float* __restrict__ x){
    const int gi = blockIdx.x, ck = blockIdx.y, t = threadIdx.x;
    const float4* p = (const float4*)(x + (size_t)gi*524288 + (size_t)ck*65536);
    float s = 0.f, ss = 0.f;
    #pragma unroll 4
    for (int it = 0; it < 64; ++it){
        float4 v = p[it*256 + t];
        s  += v.x + v.y + v.z + v.w;
        ss += v.x*v.x + v.y*v.y + v.z*v.z + v.w*v.w;
    }
    #pragma unroll
    for (int d = 16; d; d >>= 1){
        s  += __shfl_xor_sync(0xffffffffu, s, d);
        ss += __shfl_xor_sync(0xffffffffu, ss, d);
    }
    __shared__ float sh[16];
    if ((t & 31) == 0){ sh[t>>5] = s; sh[8 + (t>>5)] = ss; }
    __syncthreads();
    if (t == 0){
        float S = 0.f, SS = 0.f;
        for (int i = 0; i < 8; ++i){ S += sh[i]; SS += sh[8+i]; }
        g_part[gi][ck][0] = S; g_part[gi][ck][1] = SS;
    }
}

__global__ void k_statfin(){
    const int t = threadIdx.x;
    float S = 0.f, SS = 0.f;
    for (int i = 0; i < 8; ++i){ S += g_part[t][i][0]; SS += g_part[t][i][1]; }
    const float inv = 1.f/524288.f;
    const float m = S*inv;
    const float v = SS*inv - m*m;
    g_mean[t] = m;
    g_rstd[t] = rsqrtf(v + 1e-5f);
}

// ---------------- fused GroupNorm-apply + QKV GEMM ---------------------------
// 512 threads / 16 warps. CTA tile 256 tok x 128 m, 6 M-iterations.
// Warp tile 64 tok x 32 m. A-operand = tokens (Bs) so D = [tok][m]:
// direct bf16x2 stores to the token-major qkv buffer (no smem staging).
__global__ __launch_bounds__(512, 1) void k_qkv(
    const float* __restrict__ x, const float* __restrict__ gamma,
    const float* __restrict__ beta, const float* __restrict__ bqkv)
{
    extern __shared__ __nv_bfloat16 sm[];
    __nv_bfloat16* Bs = sm;               // [256 tok][PITCH]
    __nv_bfloat16* As = sm + 256*PITCH;   // [128 m][PITCH]
    const int t  = threadIdx.x;
    const int bv = blockIdx.y;
    const int p0 = blockIdx.x * 256;
    const int lane = t & 31, warp = t >> 5;

    // ---- fill Bs: normalize x -> bf16, token-major rows (256 tokens) ----
    #pragma unroll
    for (int it = 0; it < 8; ++it){
        const int c = (it*16 + warp) * 2;
        const int gidx = bv*8 + (c >> 5);
        const float mu = g_mean[gidx], r = g_rstd[gidx];
        const float sc0 = r*gamma[c],   sh0 = beta[c]   - mu*sc0;
        const float sc1 = r*gamma[c+1], sh1 = beta[c+1] - mu*sc1;
        const float* x0 = x + ((size_t)(bv*256 + c))*HW + p0;
        const float* x1 = x0 + HW;
        #pragma unroll
        for (int i = 0; i < 8; ++i){
            const int j = i*32 + lane;
            *(__nv_bfloat162*)(Bs + j*PITCH + c) =
                __floats2bfloat162_rn(x0[j]*sc0 + sh0, x1[j]*sc1 + sh1);
        }
    }
    load_w128(As, g_wqkv, t);
    __syncthreads();

    const int g = lane >> 2, tq = lane & 3;
    const int lrow  = lane & 15;
    const int khalf = lane >> 4;
    const int twarp = (warp >> 2) * 64;   // token offset (4 groups of 64)
    const int mwarp = (warp & 3) * 32;    // m offset     (4 groups of 32)

    uint32_t aB[4], bB[2];
    #pragma unroll
    for (int i = 0; i < 4; ++i)
        aB[i] = s2u(Bs + (twarp + i*16 + lrow)*PITCH) + khalf*16;
    #pragma unroll
    for (int j = 0; j < 2; ++j)
        bB[j] = s2u(As + (mwarp + j*16 + lrow)*PITCH) + khalf*16;

    for (int mt = 0; mt < 6; ++mt){
        float acc[4][4][4];
        #pragma unroll
        for (int i=0;i<4;i++)
            #pragma unroll
            for (int j=0;j<4;j++)
                #pragma unroll
                for (int r=0;r<4;r++) acc[i][j][r]=0.f;

        #pragma unroll 2
        for (int k0 = 0; k0 < 256; k0 += 16){
            uint32_t ra[4][4], rb[2][4];
            #pragma unroll
            for (int i = 0; i < 4; ++i) ldsm4(ra[i], aB[i] + k0*2);
            #pragma unroll
            for (int j = 0; j < 2; ++j) ldsm4(rb[j], bB[j] + k0*2);
            #pragma unroll
            for (int i = 0; i < 4; ++i)
                #pragma unroll
                for (int j = 0; j < 4; ++j)
                    mma_bf16(acc[i][j], ra[i],
                             rb[j>>1][j&1], rb[j>>1][2 + (j&1)]);
        }
        __syncthreads();
        if (mt < 5) load_w128(As, g_wqkv + (size_t)(mt + 1)*128*256, t);

        // direct epilogue: bias + bf16x2 pack + token-major global stores
        const float* bb = bqkv + mt*128 + mwarp;
        #pragma unroll
        for (int i = 0; i < 4; ++i){
            const int tokA = p0 + twarp + i*16 + g;
            __nv_bfloat16* d0 = g_qkvT + ((size_t)(bv*HW + tokA))*768 + mt*128 + mwarp;
            __nv_bfloat16* d1 = d0 + (size_t)8*768;
            #pragma unroll
            for (int j = 0; j < 4; ++j){
                const int m0 = j*8 + tq*2;
                *(__nv_bfloat162*)(d0 + m0) =
                    __floats2bfloat162_rn(acc[i][j][0] + bb[m0], acc[i][j][1] + bb[m0+1]);
                *(__nv_bfloat162*)(d1 + m0) =
                    __floats2bfloat162_rn(acc[i][j][2] + bb[m0], acc[i][j][3] + bb[m0+1]);
            }
        }
        __syncthreads();
    }
}

// ---------------- fused attention + proj GEMM + bias + residual ---------------
// CTA: one batch-pair x 128 pixels (= 256 tokens, both views).
// Phase 1: warp-per-pixel 2x2 cross-view attention, ao written into Bs (smem).
// Phase 2: proj GEMM 256 tok x 256 ch (2 M-iterations), warp tile 32ch x 64tok,
// D = [ch][tok] -> fused bias + residual + direct float2 NCHW stores.
__global__ __launch_bounds__(512, 1) void k_proj(
    const float* __restrict__ x, const float* __restrict__ bproj, float* __restrict__ out)
{
    extern __shared__ __nv_bfloat16 sm[];
    __nv_bfloat16* Bs = sm;               // [256 tok][PITCH] attention output
    __nv_bfloat16* As = sm + 256*PITCH;   // [128 ch][PITCH] weights
    const int t  = threadIdx.x;
    const int b  = blockIdx.y;            // pair index
    const int p0 = blockIdx.x * 128;
    const int lane = t & 31, warp = t >> 5;

    // ---- phase 1: attention (8 pixels per warp) ----
    {
        const int off = (lane >> 3)*64 + (lane & 7)*8;   // channel offset
        #pragma unroll
        for (int itr = 0; itr < 8; ++itr){
            const int pix = warp*8 + itr;
            const __nv_bfloat16* r0 = g_qkvT + ((size_t)(b*2*HW + p0 + pix))*768;
            const __nv_bfloat16* r1 = r0 + (size_t)HW*768;
            float q0[8],q1[8],k0[8],k1[8],v0[8],v1[8];
            {
                uint4 u; const __nv_bfloat162* h = (const __nv_bfloat162*)&u; float2 f;
                #define LD8(dst, ptr) { u = *(const uint4*)(ptr); \
                    _Pragma("unroll") for (int e = 0; e < 4; ++e){ f = __bfloat1622float2(h[e]); dst[2*e]=f.x; dst[2*e+1]=f.y; } }
                LD8(q0, r0 + off);        LD8(q1, r1 + off);
                LD8(k0, r0 + 256 + off);  LD8(k1, r1 + 256 + off);
                LD8(v0, r0 + 512 + off);  LD8(v1, r1 + 512 + off);
                #undef LD8
            }
            float s00=0.f, s01=0.f, s10=0.f, s11=0.f;
            #pragma unroll
            for (int j = 0; j < 8; ++j){
                s00 += q0[j]*k0[j]; s01 += q0[j]*k1[j];
                s10 += q1[j]*k0[j]; s11 += q1[j]*k1[j];
            }
            #pragma unroll
            for (int d = 1; d < 8; d <<= 1){
                s00 += __shfl_xor_sync(0xffffffffu, s00, d);
                s01 += __shfl_xor_sync(0xffffffffu, s01, d);
                s10 += __shfl_xor_sync(0xffffffffu, s10, d);
                s11 += __shfl_xor_sync(0xffffffffu, s11, d);
            }
            const float sc = 0.125f;
            const float l00=s00*sc, l01=s01*sc, l10=s10*sc, l11=s11*sc;
            const float m0 = fmaxf(l00,l01), m1 = fmaxf(l10,l11);
            const float e00=__expf(l00-m0), e01=__expf(l01-m0);
            const float e10=__expf(l10-m1), e11=__expf(l11-m1);
            const float i0 = 1.f/(e00+e01), i1 = 1.f/(e10+e11);
            const float a00=e00*i0, a01=e01*i0, a10=e10*i1, a11=e11*i1;
            __align__(16) __nv_bfloat16 o0[8], o1[8];
            #pragma unroll
            for (int j = 0; j < 8; ++j){
                o0[j] = __float2bfloat16(a00*v0[j] + a01*v1[j]);
                o1[j] = __float2bfloat16(a10*v0[j] + a11*v1[j]);
            }
            *(uint4*)(Bs + pix*PITCH + off)         = *(const uint4*)o0;
            *(uint4*)(Bs + (128 + pix)*PITCH + off) = *(const uint4*)o1;
        }
    }
    load_w128(As, g_wproj, t);
    __syncthreads();

    // ---- phase 2: proj GEMM ----
    const int g = lane >> 2, tq = lane & 3;
    const int lrow  = lane & 15;
    const int khalf = lane >> 4;
    const int mwarp = (warp & 3) * 32;    // channel offset (4 groups of 32)
    const int twarp = (warp >> 2) * 64;   // token offset   (4 groups of 64)
    const int view  = twarp >> 7;         // 0 or 1
    const int pixb  = twarp & 127;

    uint32_t aB[2], bB[4];
    #pragma unroll
    for (int i = 0; i < 2; ++i)
        aB[i] = s2u(As + (mwarp + i*16 + lrow)*PITCH) + khalf*16;
    #pragma unroll
    for (int j = 0; j < 4; ++j)
        bB[j] = s2u(Bs + (twarp + j*16 + lrow)*PITCH) + khalf*16;

    for (int mt = 0; mt < 2; ++mt){
        float acc[2][8][4];
        #pragma unroll
        for (int i=0;i<2;i++)
            #pragma unroll
            for (int j=0;j<8;j++)
                #pragma unroll
                for (int r=0;r<4;r++) acc[i][j][r]=0.f;

        #pragma unroll 2
        for (int k0 = 0; k0 < 256; k0 += 16){
            uint32_t ra[2][4], rb[4][4];
            #pragma unroll
            for (int i = 0; i < 2; ++i) ldsm4(ra[i], aB[i] + k0*2);
            #pragma unroll
            for (int j = 0; j < 4; ++j) ldsm4(rb[j], bB[j] + k0*2);
            #pragma unroll
            for (int i = 0; i < 2; ++i)
                #pragma unroll
                for (int j = 0; j < 8; ++j)
                    mma_bf16(acc[i][j], ra[i],
                             rb[j>>1][j&1], rb[j>>1][2 + (j&1)]);
        }
        __syncthreads();
        if (mt == 0) load_w128(As, g_wproj + 128*256, t);

        // fused epilogue: bias + residual + direct float2 NCHW stores
        #pragma unroll
        for (int i = 0; i < 2; ++i){
            const int ch0 = mt*128 + mwarp + i*16 + g;
            const int ch1 = ch0 + 8;
            const float b0 = bproj[ch0], b1 = bproj[ch1];
            const size_t base0 = ((size_t)((b*2 + view)*256 + ch0))*HW + p0 + pixb;
            const size_t base1 = ((size_t)((b*2 + view)*256 + ch1))*HW + p0 + pixb;
            #pragma unroll
            for (int j = 0; j < 8; ++j){
                const int tk = j*8 + tq*2;
                float2 xv0 = *(const float2*)(x + base0 + tk);
                float2 xv1 = *(const float2*)(x + base1 + tk);
                *(float2*)(out + base0 + tk) =
                    make_float2(xv0.x + acc[i][j][0] + b0, xv0.y + acc[i][j][1] + b0);
                *(float2*)(out + base1 + tk) =
                    make_float2(xv1.x + acc[i][j][2] + b1, xv1.y + acc[i][j][3] + b1);
            }
        }
        __syncthreads();
    }
}

// ---------------- launch -------------------------------------------------------
extern "C" void kernel_launch(void* const* d_in, const int* in_sizes, int n_in,
                              void* d_out, int out_size)
{
    const float* x     = (const float*)d_in[0];
    const float* gam   = (const float*)d_in[1];
    const float* bet   = (const float*)d_in[2];
    const float* wqkv  = (const float*)d_in[3];
    const float* bqkv  = (const float*)d_in[4];
    const float* wproj = (const float*)d_in[5];
    const float* bproj = (const float*)d_in[6];
    float* out = (float*)d_out;

    cudaFuncSetAttribute(k_qkv,  cudaFuncAttributeMaxDynamicSharedMemorySize, GEMM_SMEM);
    cudaFuncSetAttribute(k_proj, cudaFuncAttributeMaxDynamicSharedMemorySize, GEMM_SMEM);

    k_convert<<<768, 256>>>(wqkv, wproj);
    k_stats<<<dim3(64, 8), 256>>>(x);
    k_statfin<<<1, 64>>>();
    k_qkv<<<dim3(64, 8), 512, GEMM_SMEM>>>(x, gam, bet, bqkv);
    k_proj<<<dim3(128, 4), 512, GEMM_SMEM>>>(x, bproj, out);
}

// round 11
// speedup vs baseline: 1.0569x; 1.0569x over previous
#include <cuda_runtime.h>
#include <cuda_bf16.h>
#include <cstdint>

#define HW 16384
#define PITCH 264
#define GEMM_SMEM ((256*PITCH + 128*PITCH)*2)   // 384 rows of PITCH bf16

// ---------------- scratch (device globals; no allocations allowed) ----------
__device__ __nv_bfloat16 g_qkvT[(size_t)8*HW*768];   // [bv][p][768] bf16
__device__ __nv_bfloat16 g_wqkv[768*256];
__device__ __nv_bfloat16 g_wproj[256*256];
__device__ float g_part[64][8][2];
__device__ float g_mean[64];
__device__ float g_rstd[64];

// ---------------- helpers ----------------------------------------------------
__device__ __forceinline__ uint32_t s2u(const void* p){
    return (uint32_t)__cvta_generic_to_shared(p);
}
__device__ __forceinline__ void ldsm4(uint32_t r[4], uint32_t addr){
    asm volatile("ldmatrix.sync.aligned.m8n8.x4.shared.b16 {%0,%1,%2,%3}, [%4];"
        : "=r"(r[0]), "=r"(r[1]), "=r"(r[2]), "=r"(r[3]) : "r"(addr));
}
__device__ __forceinline__ void mma_bf16(float c[4], const uint32_t a[4],
                                         uint32_t b0, uint32_t b1){
    asm volatile(
      "mma.sync.aligned.m16n8k16.row.col.f32.bf16.bf16.f32 "
      "{%0,%1,%2,%3},{%4,%5,%6,%7},{%8,%9},{%0,%1,%2,%3};\n"
      : "+f"(c[0]), "+f"(c[1]), "+f"(c[2]), "+f"(c[3])
      : "r"(a[0]), "r"(a[1]), "r"(a[2]), "r"(a[3]), "r"(b0), "r"(b1));
}

// load [256 m][256 k] weight tile into smem [256][PITCH], 256 threads
__device__ __forceinline__ void load_w256(__nv_bfloat16* As,
                                          const __nv_bfloat16* W, int t){
    #pragma unroll
    for (int it = 0; it < 32; ++it){
        const int lin = it*256 + t;
        const int r = lin >> 5, k16 = lin & 31;
        *(uint4*)(As + r*PITCH + k16*8) = *(const uint4*)(W + r*256 + k16*8);
    }
}
// load [128 m][256 k] weight tile into smem [128][PITCH], 512 threads
__device__ __forceinline__ void load_w128(__nv_bfloat16* As,
                                          const __nv_bfloat16* W, int t){
    #pragma unroll
    for (int it = 0; it < 8; ++it){
        const int lin = it*512 + t;
        const int r = lin >> 5, k16 = lin & 31;
        *(uint4*)(As + r*PITCH + k16*8) = *(const uint4*)(W + r*256 + k16*8);
    }
}

// ---------------- weight convert ---------------------------------------------
__global__ void k_convert(const float* __restrict__ wq, const float* __restrict__ wp){
    int i = blockIdx.x*256 + threadIdx.x;
    if (i < 768*256) g_wqkv[i]  = __float2bfloat16(wq[i]);
    if (i < 256*256) g_wproj[i] = __float2bfloat16(wp[i]);
}

// ---------------- GroupNorm statistics ---------------------------------------
__global__ void k_stats(const float* __restrict__ x){
    const int gi = blockIdx.x, ck = blockIdx.y, t = threadIdx.x;
    const float4* p = (const float4*)(x + (size_t)gi*524288 + (size_t)ck*65536);
    float s = 0.f, ss = 0.f;
    #pragma unroll 4
    for (int it = 0; it < 64; ++it){
        float4 v = p[it*256 + t];
        s  += v.x + v.y + v.z + v.w;
        ss += v.x*v.x + v.y*v.y + v.z*v.z + v.w*v.w;
    }
    #pragma unroll
    for (int d = 16; d; d >>= 1){
        s  += __shfl_xor_sync(0xffffffffu, s, d);
        ss += __shfl_xor_sync(0xffffffffu, ss, d);
    }
    __shared__ float sh[16];
    if ((t & 31) == 0){ sh[t>>5] = s; sh[8 + (t>>5)] = ss; }
    __syncthreads();
    if (t == 0){
        float S = 0.f, SS = 0.f;
        for (int i = 0; i < 8; ++i){ S += sh[i]; SS += sh[8+i]; }
        g_part[gi][ck][0] = S; g_part[gi][ck][1] = SS;
    }
}

__global__ void k_statfin(){
    const int t = threadIdx.x;
    float S = 0.f, SS = 0.f;
    for (int i = 0; i < 8; ++i){ S += g_part[t][i][0]; SS += g_part[t][i][1]; }
    const float inv = 1.f/524288.f;
    const float m = S*inv;
    const float v = SS*inv - m*m;
    g_mean[t] = m;
    g_rstd[t] = rsqrtf(v + 1e-5f);
}

// ---------------- fused GroupNorm-apply + QKV GEMM ---------------------------
// 256 threads / 8 warps, warp tile 64 tok x 64 m, CTA tile 128 tok x 256 m,
// 3 M-iterations. Fragment double-buffering: slab k+1 LDSMs issue while
// slab k's 32 MMAs retire. D = [tok][m] -> direct bf16x2 token-major stores.
__global__ __launch_bounds__(256, 1) void k_qkv(
    const float* __restrict__ x, const float* __restrict__ gamma,
    const float* __restrict__ beta, const float* __restrict__ bqkv)
{
    extern __shared__ __nv_bfloat16 sm[];
    __nv_bfloat16* Bs = sm;               // [128 tok][PITCH]
    __nv_bfloat16* As = sm + 128*PITCH;   // [256 m][PITCH]
    const int t  = threadIdx.x;
    const int bv = blockIdx.y;
    const int p0 = blockIdx.x * 128;
    const int lane = t & 31, warp = t >> 5;

    // ---- fill Bs: normalize x -> bf16, token-major rows ----
    #pragma unroll
    for (int it = 0; it < 16; ++it){
        const int c = (it*8 + warp) * 2;
        const int gidx = bv*8 + (c >> 5);
        const float mu = g_mean[gidx], r = g_rstd[gidx];
        const float sc0 = r*gamma[c],   sh0 = beta[c]   - mu*sc0;
        const float sc1 = r*gamma[c+1], sh1 = beta[c+1] - mu*sc1;
        const float* x0 = x + ((size_t)(bv*256 + c))*HW + p0;
        const float* x1 = x0 + HW;
        #pragma unroll
        for (int i = 0; i < 4; ++i){
            const int j = i*32 + lane;
            *(__nv_bfloat162*)(Bs + j*PITCH + c) =
                __floats2bfloat162_rn(x0[j]*sc0 + sh0, x1[j]*sc1 + sh1);
        }
    }
    load_w256(As, g_wqkv, t);
    __syncthreads();

    const int g = lane >> 2, tq = lane & 3;
    const int lrow  = lane & 15;
    const int khalf = lane >> 4;
    const int twarp = (warp >> 2) * 64;   // token offset (2 groups)
    const int mwarp = (warp & 3) * 64;    // m offset within 256 (4 groups)

    uint32_t aB[4], bB[4];
    #pragma unroll
    for (int i = 0; i < 4; ++i)
        aB[i] = s2u(Bs + (twarp + i*16 + lrow)*PITCH) + khalf*16;
    #pragma unroll
    for (int j = 0; j < 4; ++j)
        bB[j] = s2u(As + (mwarp + j*16 + lrow)*PITCH) + khalf*16;

    #pragma unroll 1
    for (int mt = 0; mt < 3; ++mt){
        float acc[4][8][4];
        #pragma unroll
        for (int i=0;i<4;i++)
            #pragma unroll
            for (int j=0;j<8;j++)
                #pragma unroll
                for (int r=0;r<4;r++) acc[i][j][r]=0.f;

        uint32_t ra[2][4][4], rb[2][4][4];
        #pragma unroll
        for (int i = 0; i < 4; ++i) ldsm4(ra[0][i], aB[i]);
        #pragma unroll
        for (int j = 0; j < 4; ++j) ldsm4(rb[0][j], bB[j]);

        #pragma unroll
        for (int ks = 0; ks < 16; ++ks){
            const int cur = ks & 1, nxt = cur ^ 1;
            if (ks < 15){
                #pragma unroll
                for (int i = 0; i < 4; ++i) ldsm4(ra[nxt][i], aB[i] + (ks+1)*32);
                #pragma unroll
                for (int j = 0; j < 4; ++j) ldsm4(rb[nxt][j], bB[j] + (ks+1)*32);
            }
            #pragma unroll
            for (int i = 0; i < 4; ++i)
                #pragma unroll
                for (int j = 0; j < 8; ++j)
                    mma_bf16(acc[i][j], ra[cur][i],
                             rb[cur][j>>1][j&1], rb[cur][j>>1][2 + (j&1)]);
        }
        __syncthreads();
        if (mt < 2) load_w256(As, g_wqkv + (size_t)(mt + 1)*256*256, t);

        // direct epilogue: bias + bf16x2 pack + token-major global stores
        const float* bb = bqkv + mt*256 + mwarp;
        #pragma unroll
        for (int i = 0; i < 4; ++i){
            const int tokA = p0 + twarp + i*16 + g;
            __nv_bfloat16* d0 = g_qkvT + ((size_t)(bv*HW + tokA))*768 + mt*256 + mwarp;
            __nv_bfloat16* d1 = d0 + (size_t)8*768;
            #pragma unroll
            for (int j = 0; j < 8; ++j){
                const int m0 = j*8 + tq*2;
                *(__nv_bfloat162*)(d0 + m0) =
                    __floats2bfloat162_rn(acc[i][j][0] + bb[m0], acc[i][j][1] + bb[m0+1]);
                *(__nv_bfloat162*)(d1 + m0) =
                    __floats2bfloat162_rn(acc[i][j][2] + bb[m0], acc[i][j][3] + bb[m0+1]);
            }
        }
        __syncthreads();
    }
}

// ---------------- fused attention + proj GEMM + bias + residual ---------------
// CTA: one batch-pair x 128 pixels (= 256 tokens, both views). 512 threads.
// Phase 1: warp-per-pixel 2x2 cross-view attention, ao -> Bs (smem only).
// Phase 2: proj GEMM 256 tok x 256 ch, warp tile 32ch x 64tok, fragment
// double-buffered; fused bias + residual + direct float2 NCHW stores.
__global__ __launch_bounds__(512, 1) void k_proj(
    const float* __restrict__ x, const float* __restrict__ bproj, float* __restrict__ out)
{
    extern __shared__ __nv_bfloat16 sm[];
    __nv_bfloat16* Bs = sm;               // [256 tok][PITCH] attention output
    __nv_bfloat16* As = sm + 256*PITCH;   // [128 ch][PITCH] weights
    const int t  = threadIdx.x;
    const int b  = blockIdx.y;            // pair index
    const int p0 = blockIdx.x * 128;
    const int lane = t & 31, warp = t >> 5;

    // ---- phase 1: attention (8 pixels per warp) ----
    {
        const int off = (lane >> 3)*64 + (lane & 7)*8;   // channel offset
        #pragma unroll 2
        for (int itr = 0; itr < 8; ++itr){
            const int pix = warp*8 + itr;
            const __nv_bfloat16* r0 = g_qkvT + ((size_t)(b*2*HW + p0 + pix))*768;
            const __nv_bfloat16* r1 = r0 + (size_t)HW*768;
            float q0[8],q1[8],k0[8],k1[8],v0[8],v1[8];
            {
                uint4 u; const __nv_bfloat162* h = (const __nv_bfloat162*)&u; float2 f;
                #define LD8(dst, ptr) { u = *(const uint4*)(ptr); \
                    _Pragma("unroll") for (int e = 0; e < 4; ++e){ f = __bfloat1622float2(h[e]); dst[2*e]=f.x; dst[2*e+1]=f.y; } }
                LD8(q0, r0 + off);        LD8(q1, r1 + off);
                LD8(k0, r0 + 256 + off);  LD8(k1, r1 + 256 + off);
                LD8(v0, r0 + 512 + off);  LD8(v1, r1 + 512 + off);
                #undef LD8
            }
            float s00=0.f, s01=0.f, s10=0.f, s11=0.f;
            #pragma unroll
            for (int j = 0; j < 8; ++j){
                s00 += q0[j]*k0[j]; s01 += q0[j]*k1[j];
                s10 += q1[j]*k0[j]; s11 += q1[j]*k1[j];
            }
            #pragma unroll
            for (int d = 1; d < 8; d <<= 1){
                s00 += __shfl_xor_sync(0xffffffffu, s00, d);
                s01 += __shfl_xor_sync(0xffffffffu, s01, d);
                s10 += __shfl_xor_sync(0xffffffffu, s10, d);
                s11 += __shfl_xor_sync(0xffffffffu, s11, d);
            }
            const float sc = 0.125f;
            const float l00=s00*sc, l01=s01*sc, l10=s10*sc, l11=s11*sc;
            const float m0 = fmaxf(l00,l01), m1 = fmaxf(l10,l11);
            const float e00=__expf(l00-m0), e01=__expf(l01-m0);
            const float e10=__expf(l10-m1), e11=__expf(l11-m1);
            const float i0 = 1.f/(e00+e01), i1 = 1.f/(e10+e11);
            const float a00=e00*i0, a01=e01*i0, a10=e10*i1, a11=e11*i1;
            __align__(16) __nv_bfloat16 o0[8], o1[8];
            #pragma unroll
            for (int j = 0; j < 8; ++j){
                o0[j] = __float2bfloat16(a00*v0[j] + a01*v1[j]);
                o1[j] = __float2bfloat16(a10*v0[j] + a11*v1[j]);
            }
            *(uint4*)(Bs + pix*PITCH + off)         = *(const uint4*)o0;
            *(uint4*)(Bs + (128 + pix)*PITCH + off) = *(const uint4*)o1;
        }
    }
    load_w128(As, g_wproj, t);
    __syncthreads();

    // ---- phase 2: proj GEMM (double-buffered fragments) ----
    const int g = lane >> 2, tq = lane & 3;
    const int lrow  = lane & 15;
    const int khalf = lane >> 4;
    const int mwarp = (warp & 3) * 32;    // channel offset (4 groups of 32)
    const int twarp = (warp >> 2) * 64;   // token offset   (4 groups of 64)
    const int view  = twarp >> 7;         // 0 or 1
    const int pixb  = twarp & 127;

    uint32_t aB[2], bB[4];
    #pragma unroll
    for (int i = 0; i < 2; ++i)
        aB[i] = s2u(As + (mwarp + i*16 + lrow)*PITCH) + khalf*16;
    #pragma unroll
    for (int j = 0; j < 4; ++j)
        bB[j] = s2u(Bs + (twarp + j*16 + lrow)*PITCH) + khalf*16;

    #pragma unroll 1
    for (int mt = 0; mt < 2; ++mt){
        float acc[2][8][4];
        #pragma unroll
        for (int i=0;i<2;i++)
            #pragma unroll
            for (int j=0;j<8;j++)
                #pragma unroll
                for (int r=0;r<4;r++) acc[i][j][r]=0.f;

        uint32_t ra[2][2][4], rb[2][4][4];
        #pragma unroll
        for (int i = 0; i < 2; ++i) ldsm4(ra[0][i], aB[i]);
        #pragma unroll
        for (int j = 0; j < 4; ++j) ldsm4(rb[0][j], bB[j]);

        #pragma unroll
        for (int ks = 0; ks < 16; ++ks){
            const int cur = ks & 1, nxt = cur ^ 1;
            if (ks < 15){
                #pragma unroll
                for (int i = 0; i < 2; ++i) ldsm4(ra[nxt][i], aB[i] + (ks+1)*32);
                #pragma unroll
                for (int j = 0; j < 4; ++j) ldsm4(rb[nxt][j], bB[j] + (ks+1)*32);
            }
            #pragma unroll
            for (int i = 0; i < 2; ++i)
                #pragma unroll
                for (int j = 0; j < 8; ++j)
                    mma_bf16(acc[i][j], ra[cur][i],
                             rb[cur][j>>1][j&1], rb[cur][j>>1][2 + (j&1)]);
        }
        __syncthreads();
        if (mt == 0) load_w128(As, g_wproj + 128*256, t);

        // fused epilogue: bias + residual + direct float2 NCHW stores
        #pragma unroll
        for (int i = 0; i < 2; ++i){
            const int ch0 = mt*128 + mwarp + i*16 + g;
            const int ch1 = ch0 + 8;
            const float b0 = bproj[ch0], b1 = bproj[ch1];
            const size_t base0 = ((size_t)((b*2 + view)*256 + ch0))*HW + p0 + pixb;
            const size_t base1 = ((size_t)((b*2 + view)*256 + ch1))*HW + p0 + pixb;
            #pragma unroll
            for (int j = 0; j < 8; ++j){
                const int tk = j*8 + tq*2;
                float2 xv0 = *(const float2*)(x + base0 + tk);
                float2 xv1 = *(const float2*)(x + base1 + tk);
                *(float2*)(out + base0 + tk) =
                    make_float2(xv0.x + acc[i][j][0] + b0, xv0.y + acc[i][j][1] + b0);
                *(float2*)(out + base1 + tk) =
                    make_float2(xv1.x + acc[i][j][2] + b1, xv1.y + acc[i][j][3] + b1);
            }
        }
        __syncthreads();
    }
}

// ---------------- launch -------------------------------------------------------
extern "C" void kernel_launch(void* const* d_in, const int* in_sizes, int n_in,
                              void* d_out, int out_size)
{
    const float* x     = (const float*)d_in[0];
    const float* gam   = (const float*)d_in[1];
    const float* bet   = (const float*)d_in[2];
    const float* wqkv  = (const float*)d_in[3];
    const float* bqkv  = (const float*)d_in[4];
    const float* wproj = (const float*)d_in[5];
    const float* bproj = (const float*)d_in[6];
    float* out = (float*)d_out;

    cudaFuncSetAttribute(k_qkv,  cudaFuncAttributeMaxDynamicSharedMemorySize, GEMM_SMEM);
    cudaFuncSetAttribute(k_proj, cudaFuncAttributeMaxDynamicSharedMemorySize, GEMM_SMEM);

    k_convert<<<768, 256>>>(wqkv, wproj);
    k_stats<<<dim3(64, 8), 256>>>(x);
    k_statfin<<<1, 64>>>();
    k_qkv<<<dim3(128, 8), 256, GEMM_SMEM>>>(x, gam, bet, bqkv);
    k_proj<<<dim3(128, 4), 512, GEMM_SMEM>>>(x, bproj, out);
}

// round 12
// speedup vs baseline: 1.1426x; 1.0810x over previous
#include <cuda_runtime.h>
#include <cuda_bf16.h>
#include <cstdint>

#define HW 16384
#define PCH 136                    // elems per 128-k chunk row (128 + 8 pad)
#define CHUNK (128*PCH)            // elems per 128-row chunk
#define CHUNK_B (CHUNK*2)          // bytes per chunk (34816)
#define FUSE_SMEM (3*CHUNK_B)      // Bs 2 chunks + As 1 chunk = 104448 B

// ---------------- scratch (device globals; no allocations allowed) ----------
__device__ __nv_bfloat16 g_qkvT[(size_t)8*HW*768];   // [bv][p][768] bf16
__device__ __nv_bfloat16 g_wqkv[768*256];
__device__ __nv_bfloat16 g_wproj[256*256];
__device__ float g_part[64][8][2];
__device__ float g_mean[64];
__device__ float g_rstd[64];

// ---------------- helpers ----------------------------------------------------
__device__ __forceinline__ uint32_t s2u(const void* p){
    return (uint32_t)__cvta_generic_to_shared(p);
}
__device__ __forceinline__ void ldsm4(uint32_t r[4], uint32_t addr){
    asm volatile("ldmatrix.sync.aligned.m8n8.x4.shared.b16 {%0,%1,%2,%3}, [%4];"
        : "=r"(r[0]), "=r"(r[1]), "=r"(r[2]), "=r"(r[3]) : "r"(addr));
}
__device__ __forceinline__ void mma_bf16(float c[4], const uint32_t a[4],
                                         uint32_t b0, uint32_t b1){
    asm volatile(
      "mma.sync.aligned.m16n8k16.row.col.f32.bf16.bf16.f32 "
      "{%0,%1,%2,%3},{%4,%5,%6,%7},{%8,%9},{%0,%1,%2,%3};\n"
      : "+f"(c[0]), "+f"(c[1]), "+f"(c[2]), "+f"(c[3])
      : "r"(a[0]), "r"(a[1]), "r"(a[2]), "r"(a[3]), "r"(b0), "r"(b1));
}

// load a [128 rows][128 k] bf16 half-K weight tile into smem [128][PCH].
// W must point at row 0, col kc*128 of a K=256 row-major weight matrix.
__device__ __forceinline__ void loadA(__nv_bfloat16* As,
                                      const __nv_bfloat16* W, int t){
    #pragma unroll
    for (int it = 0; it < 8; ++it){
        const int lin = it*256 + t;
        const int r = lin >> 4, seg = lin & 15;
        *(uint4*)(As + r*PCH + seg*8) = *(const uint4*)(W + r*256 + seg*8);
    }
}

// ---------------- weight convert ---------------------------------------------
__global__ void k_convert(const float* __restrict__ wq, const float* __restrict__ wp){
    int i = blockIdx.x*256 + threadIdx.x;
    if (i < 768*256) g_wqkv[i]  = __float2bfloat16(wq[i]);
    if (i < 256*256) g_wproj[i] = __float2bfloat16(wp[i]);
}

// ---------------- GroupNorm statistics ---------------------------------------
__global__ void k_stats(const float* __restrict__ x){
    const int gi = blockIdx.x, ck = blockIdx.y, t = threadIdx.x;
    const float4* p = (const float4*)(x + (size_t)gi*524288 + (size_t)ck*65536);
    float s = 0.f, ss = 0.f;
    #pragma unroll 4
    for (int it = 0; it < 64; ++it){
        float4 v = p[it*256 + t];
        s  += v.x + v.y + v.z + v.w;
        ss += v.x*v.x + v.y*v.y + v.z*v.z + v.w*v.w;
    }
    #pragma unroll
    for (int d = 16; d; d >>= 1){
        s  += __shfl_xor_sync(0xffffffffu, s, d);
        ss += __shfl_xor_sync(0xffffffffu, ss, d);
    }
    __shared__ float sh[16];
    if ((t & 31) == 0){ sh[t>>5] = s; sh[8 + (t>>5)] = ss; }
    __syncthreads();
    if (t == 0){
        float S = 0.f, SS = 0.f;
        for (int i = 0; i < 8; ++i){ S += sh[i]; SS += sh[8+i]; }
        g_part[gi][ck][0] = S; g_part[gi][ck][1] = SS;
    }
}

__global__ void k_statfin(){
    const int t = threadIdx.x;
    float S = 0.f, SS = 0.f;
    for (int i = 0; i < 8; ++i){ S += g_part[t][i][0]; SS += g_part[t][i][1]; }
    const float inv = 1.f/524288.f;
    const float m = S*inv;
    const float v = SS*inv - m*m;
    g_mean[t] = m;
    g_rstd[t] = rsqrtf(v + 1e-5f);
}

// ---------------- fused GroupNorm-apply + QKV GEMM ---------------------------
// 256 threads / 8 warps, 2 CTAs/SM (smem 102KB, regs <=128).
// CTA tile 128 tok x 128 m (6 M-iters), K split in 2 chunks of 128.
// Warp tile 64 tok x 32 m. D = [tok][m] -> direct bf16x2 token-major stores.
__global__ __launch_bounds__(256, 2) void k_qkv(
    const float* __restrict__ x, const float* __restrict__ gamma,
    const float* __restrict__ beta, const float* __restrict__ bqkv)
{
    extern __shared__ __nv_bfloat16 sm[];
    __nv_bfloat16* Bs = sm;               // [2 kc][128 tok][PCH]
    __nv_bfloat16* As = sm + 2*CHUNK;     // [128 m][PCH]
    const int t  = threadIdx.x;
    const int bv = blockIdx.y;
    const int p0 = blockIdx.x * 128;
    const int lane = t & 31, warp = t >> 5;

    // ---- fill Bs: normalize x -> bf16, token-major rows, 2 K-chunks ----
    #pragma unroll
    for (int it = 0; it < 16; ++it){
        const int c = (it*8 + warp) * 2;
        const int gidx = bv*8 + (c >> 5);
        const float mu = g_mean[gidx], r = g_rstd[gidx];
        const float sc0 = r*gamma[c],   sh0 = beta[c]   - mu*sc0;
        const float sc1 = r*gamma[c+1], sh1 = beta[c+1] - mu*sc1;
        const float* x0 = x + ((size_t)(bv*256 + c))*HW + p0;
        const float* x1 = x0 + HW;
        __nv_bfloat16* dst = Bs + (c >> 7)*CHUNK + (c & 127);
        #pragma unroll
        for (int i = 0; i < 4; ++i){
            const int j = i*32 + lane;
            *(__nv_bfloat162*)(dst + j*PCH) =
                __floats2bfloat162_rn(x0[j]*sc0 + sh0, x1[j]*sc1 + sh1);
        }
    }
    loadA(As, g_wqkv, t);     // (mt=0, kc=0)
    __syncthreads();

    const int g = lane >> 2, tq = lane & 3;
    const int lrow  = lane & 15;
    const int khalf = lane >> 4;
    const int twarp = (warp >> 2) * 64;   // token offset (2 groups of 64)
    const int mwarp = (warp & 3) * 32;    // m offset     (4 groups of 32)

    uint32_t aB[4], bB[2];
    #pragma unroll
    for (int i = 0; i < 4; ++i)
        aB[i] = s2u(Bs + (twarp + i*16 + lrow)*PCH) + khalf*16;
    #pragma unroll
    for (int j = 0; j < 2; ++j)
        bB[j] = s2u(As + (mwarp + j*16 + lrow)*PCH) + khalf*16;

    #pragma unroll 1
    for (int mt = 0; mt < 6; ++mt){
        float acc[4][4][4];
        #pragma unroll
        for (int i=0;i<4;i++)
            #pragma unroll
            for (int j=0;j<4;j++)
                #pragma unroll
                for (int r=0;r<4;r++) acc[i][j][r]=0.f;

        #pragma unroll 1
        for (int kc = 0; kc < 2; ++kc){
            const uint32_t boff = (uint32_t)kc * CHUNK_B;
            #pragma unroll
            for (int ks = 0; ks < 8; ++ks){
                uint32_t ra[4][4], rb[2][4];
                #pragma unroll
                for (int i = 0; i < 4; ++i) ldsm4(ra[i], aB[i] + boff + ks*32);
                #pragma unroll
                for (int j = 0; j < 2; ++j) ldsm4(rb[j], bB[j] + ks*32);
                #pragma unroll
                for (int i = 0; i < 4; ++i)
                    #pragma unroll
                    for (int j = 0; j < 4; ++j)
                        mma_bf16(acc[i][j], ra[i],
                                 rb[j>>1][j&1], rb[j>>1][2 + (j&1)]);
            }
            __syncthreads();
            // load next As half-tile; epilogue (regs->global) overlaps it
            if (kc == 0){
                loadA(As, g_wqkv + (size_t)mt*128*256 + 128, t);
            } else if (mt < 5){
                loadA(As, g_wqkv + (size_t)(mt + 1)*128*256, t);
            }
            if (kc == 1){
                const float* bb = bqkv + mt*128 + mwarp;
                #pragma unroll
                for (int i = 0; i < 4; ++i){
                    const int tokA = p0 + twarp + i*16 + g;
                    __nv_bfloat16* d0 = g_qkvT + ((size_t)(bv*HW + tokA))*768 + mt*128 + mwarp;
                    __nv_bfloat16* d1 = d0 + (size_t)8*768;
                    #pragma unroll
                    for (int j = 0; j < 4; ++j){
                        const int m0 = j*8 + tq*2;
                        *(__nv_bfloat162*)(d0 + m0) =
                            __floats2bfloat162_rn(acc[i][j][0] + bb[m0], acc[i][j][1] + bb[m0+1]);
                        *(__nv_bfloat162*)(d1 + m0) =
                            __floats2bfloat162_rn(acc[i][j][2] + bb[m0], acc[i][j][3] + bb[m0+1]);
                    }
                }
            }
            __syncthreads();
        }
    }
}

// ---------------- fused attention + proj GEMM + bias + residual ---------------
// CTA: one batch-pair x 64 pixels (128 tokens, view-major). 256 threads,
// 2 CTAs/SM. Phase 1: warp-per-pixel attention -> ao into Bs K-chunks.
// Phase 2: proj GEMM 128 tok x 256 ch (2 M-iters, 2 K-chunks), warp tile
// 32ch x 64tok; fused bias + residual + direct float2 NCHW stores.
__global__ __launch_bounds__(256, 2) void k_proj(
    const float* __restrict__ x, const float* __restrict__ bproj, float* __restrict__ out)
{
    extern __shared__ __nv_bfloat16 sm[];
    __nv_bfloat16* Bs = sm;               // [2 kc][128 tok][PCH] attention out
    __nv_bfloat16* As = sm + 2*CHUNK;     // [128 ch][PCH] weights
    const int t  = threadIdx.x;
    const int b  = blockIdx.y;            // pair index
    const int p0 = blockIdx.x * 64;
    const int lane = t & 31, warp = t >> 5;

    // ---- phase 1: attention (8 pixels per warp) ----
    {
        const int off = (lane >> 3)*64 + (lane & 7)*8;   // channel offset 0..255
        const int chunk = off >> 7, cin = off & 127;
        #pragma unroll 2
        for (int itr = 0; itr < 8; ++itr){
            const int pix = warp*8 + itr;
            const __nv_bfloat16* r0 = g_qkvT + ((size_t)(b*2*HW + p0 + pix))*768;
            const __nv_bfloat16* r1 = r0 + (size_t)HW*768;
            float q0[8],q1[8],k0[8],k1[8],v0[8],v1[8];
            {
                uint4 u; const __nv_bfloat162* h = (const __nv_bfloat162*)&u; float2 f;
                #define LD8(dst, ptr) { u = *(const uint4*)(ptr); \
                    _Pragma("unroll") for (int e = 0; e < 4; ++e){ f = __bfloat1622float2(h[e]); dst[2*e]=f.x; dst[2*e+1]=f.y; } }
                LD8(q0, r0 + off);        LD8(q1, r1 + off);
                LD8(k0, r0 + 256 + off);  LD8(k1, r1 + 256 + off);
                LD8(v0, r0 + 512 + off);  LD8(v1, r1 + 512 + off);
                #undef LD8
            }
            float s00=0.f, s01=0.f, s10=0.f, s11=0.f;
            #pragma unroll
            for (int j = 0; j < 8; ++j){
                s00 += q0[j]*k0[j]; s01 += q0[j]*k1[j];
                s10 += q1[j]*k0[j]; s11 += q1[j]*k1[j];
            }
            #pragma unroll
            for (int d = 1; d < 8; d <<= 1){
                s00 += __shfl_xor_sync(0xffffffffu, s00, d);
                s01 += __shfl_xor_sync(0xffffffffu, s01, d);
                s10 += __shfl_xor_sync(0xffffffffu, s10, d);
                s11 += __shfl_xor_sync(0xffffffffu, s11, d);
            }
            const float sc = 0.125f;
            const float l00=s00*sc, l01=s01*sc, l10=s10*sc, l11=s11*sc;
            const float m0 = fmaxf(l00,l01), m1 = fmaxf(l10,l11);
            const float e00=__expf(l00-m0), e01=__expf(l01-m0);
            const float e10=__expf(l10-m1), e11=__expf(l11-m1);
            const float i0 = 1.f/(e00+e01), i1 = 1.f/(e10+e11);
            const float a00=e00*i0, a01=e01*i0, a10=e10*i1, a11=e11*i1;
            __align__(16) __nv_bfloat16 o0[8], o1[8];
            #pragma unroll
            for (int j = 0; j < 8; ++j){
                o0[j] = __float2bfloat16(a00*v0[j] + a01*v1[j]);
                o1[j] = __float2bfloat16(a10*v0[j] + a11*v1[j]);
            }
            // tokens: view0 -> pix, view1 -> 64+pix
            *(uint4*)(Bs + chunk*CHUNK + pix*PCH + cin)        = *(const uint4*)o0;
            *(uint4*)(Bs + chunk*CHUNK + (64 + pix)*PCH + cin) = *(const uint4*)o1;
        }
    }
    loadA(As, g_wproj, t);    // (mt=0, kc=0)
    __syncthreads();

    // ---- phase 2: proj GEMM ----
    const int g = lane >> 2, tq = lane & 3;
    const int lrow  = lane & 15;
    const int khalf = lane >> 4;
    const int mwarp = (warp & 3) * 32;    // channel offset (4 groups of 32)
    const int twarp = (warp >> 2) * 64;   // token offset (2 groups: view0/view1)
    const int view  = warp >> 2;

    uint32_t aB[2], bB[4];
    #pragma unroll
    for (int i = 0; i < 2; ++i)
        aB[i] = s2u(As + (mwarp + i*16 + lrow)*PCH) + khalf*16;
    #pragma unroll
    for (int j = 0; j < 4; ++j)
        bB[j] = s2u(Bs + (twarp + j*16 + lrow)*PCH) + khalf*16;

    #pragma unroll 1
    for (int mt = 0; mt < 2; ++mt){
        float acc[2][8][4];
        #pragma unroll
        for (int i=0;i<2;i++)
            #pragma unroll
            for (int j=0;j<8;j++)
                #pragma unroll
                for (int r=0;r<4;r++) acc[i][j][r]=0.f;

        #pragma unroll 1
        for (int kc = 0; kc < 2; ++kc){
            const uint32_t boff = (uint32_t)kc * CHUNK_B;
            #pragma unroll
            for (int ks = 0; ks < 8; ++ks){
                uint32_t ra[2][4], rb[4][4];
                #pragma unroll
                for (int i = 0; i < 2; ++i) ldsm4(ra[i], aB[i] + ks*32);
                #pragma unroll
                for (int j = 0; j < 4; ++j) ldsm4(rb[j], bB[j] + boff + ks*32);
                #pragma unroll
                for (int i = 0; i < 2; ++i)
                    #pragma unroll
                    for (int j = 0; j < 8; ++j)
                        mma_bf16(acc[i][j], ra[i],
                                 rb[j>>1][j&1], rb[j>>1][2 + (j&1)]);
            }
            __syncthreads();
            if (kc == 0){
                loadA(As, g_wproj + (size_t)mt*128*256 + 128, t);
            } else if (mt == 0){
                loadA(As, g_wproj + (size_t)128*256, t);
            }
            if (kc == 1){
                #pragma unroll
                for (int i = 0; i < 2; ++i){
                    const int ch0 = mt*128 + mwarp + i*16 + g;
                    const int ch1 = ch0 + 8;
                    const float b0 = bproj[ch0], b1 = bproj[ch1];
                    const size_t base0 = ((size_t)((b*2 + view)*256 + ch0))*HW + p0;
                    const size_t base1 = ((size_t)((b*2 + view)*256 + ch1))*HW + p0;
                    #pragma unroll
                    for (int j = 0; j < 8; ++j){
                        const int tk = j*8 + tq*2;
                        float2 xv0 = *(const float2*)(x + base0 + tk);
                        float2 xv1 = *(const float2*)(x + base1 + tk);
                        *(float2*)(out + base0 + tk) =
                            make_float2(xv0.x + acc[i][j][0] + b0, xv0.y + acc[i][j][1] + b0);
                        *(float2*)(out + base1 + tk) =
                            make_float2(xv1.x + acc[i][j][2] + b1, xv1.y + acc[i][j][3] + b1);
                    }
                }
            }
            __syncthreads();
        }
    }
}

// ---------------- launch -------------------------------------------------------
extern "C" void kernel_launch(void* const* d_in, const int* in_sizes, int n_in,
                              void* d_out, int out_size)
{
    const float* x     = (const float*)d_in[0];
    const float* gam   = (const float*)d_in[1];
    const float* bet   = (const float*)d_in[2];
    const float* wqkv  = (const float*)d_in[3];
    const float* bqkv  = (const float*)d_in[4];
    const float* wproj = (const float*)d_in[5];
    const float* bproj = (const float*)d_in[6];
    float* out = (float*)d_out;

    cudaFuncSetAttribute(k_qkv,  cudaFuncAttributeMaxDynamicSharedMemorySize, FUSE_SMEM);
    cudaFuncSetAttribute(k_proj, cudaFuncAttributeMaxDynamicSharedMemorySize, FUSE_SMEM);

    k_convert<<<768, 256>>>(wqkv, wproj);
    k_stats<<<dim3(64, 8), 256>>>(x);
    k_statfin<<<1, 64>>>();
    k_qkv<<<dim3(128, 8), 256, FUSE_SMEM>>>(x, gam, bet, bqkv);
    k_proj<<<dim3(256, 4), 256, FUSE_SMEM>>>(x, bproj, out);
}

// round 13
// speedup vs baseline: 1.1959x; 1.0467x over previous
#include <cuda_runtime.h>
#include <cuda_fp16.h>
#include <cstdint>

#define HW 16384
#define PCH 136                    // elems per 128-k chunk row (128 + 8 pad)
#define CHUNK (128*PCH)            // elems per 128-row chunk
#define CHUNK_B (CHUNK*2)          // bytes per chunk (34816)
#define FUSE_SMEM (3*CHUNK_B)      // Bs 2 chunks + As 1 chunk = 104448 B

// ---------------- scratch (device globals; no allocations allowed) ----------
__device__ __half g_qkvT[(size_t)8*HW*768];   // [bv][p][768] fp16
__device__ __half g_wqkv[768*256];
__device__ __half g_wproj[256*256];
__device__ float g_part[64][8][2];
__device__ float g_mean[64];
__device__ float g_rstd[64];

// ---------------- helpers ----------------------------------------------------
__device__ __forceinline__ uint32_t s2u(const void* p){
    return (uint32_t)__cvta_generic_to_shared(p);
}
__device__ __forceinline__ void ldsm4(uint32_t r[4], uint32_t addr){
    asm volatile("ldmatrix.sync.aligned.m8n8.x4.shared.b16 {%0,%1,%2,%3}, [%4];"
        : "=r"(r[0]), "=r"(r[1]), "=r"(r[2]), "=r"(r[3]) : "r"(addr));
}
// fp16 inputs, fp16 accumulate (full-rate HMMA)
__device__ __forceinline__ void mma_h(uint32_t c[2], const uint32_t a[4],
                                      uint32_t b0, uint32_t b1){
    asm volatile(
      "mma.sync.aligned.m16n8k16.row.col.f16.f16.f16.f16 "
      "{%0,%1},{%2,%3,%4,%5},{%6,%7},{%0,%1};\n"
      : "+r"(c[0]), "+r"(c[1])
      : "r"(a[0]), "r"(a[1]), "r"(a[2]), "r"(a[3]), "r"(b0), "r"(b1));
}
// fp16 inputs, fp32 accumulate (proj path)
__device__ __forceinline__ void mma_f(float c[4], const uint32_t a[4],
                                      uint32_t b0, uint32_t b1){
    asm volatile(
      "mma.sync.aligned.m16n8k16.row.col.f32.f16.f16.f32 "
      "{%0,%1,%2,%3},{%4,%5,%6,%7},{%8,%9},{%0,%1,%2,%3};\n"
      : "+f"(c[0]), "+f"(c[1]), "+f"(c[2]), "+f"(c[3])
      : "r"(a[0]), "r"(a[1]), "r"(a[2]), "r"(a[3]), "r"(b0), "r"(b1));
}

// load a [128 rows][128 k] fp16 half-K weight tile into smem [128][PCH].
__device__ __forceinline__ void loadA(__half* As, const __half* W, int t){
    #pragma unroll
    for (int it = 0; it < 8; ++it){
        const int lin = it*256 + t;
        const int r = lin >> 4, seg = lin & 15;
        *(uint4*)(As + r*PCH + seg*8) = *(const uint4*)(W + r*256 + seg*8);
    }
}

// ---------------- weight convert ---------------------------------------------
__global__ void k_convert(const float* __restrict__ wq, const float* __restrict__ wp){
    int i = blockIdx.x*256 + threadIdx.x;
    if (i < 768*256) g_wqkv[i]  = __float2half(wq[i]);
    if (i < 256*256) g_wproj[i] = __float2half(wp[i]);
}

// ---------------- GroupNorm statistics ---------------------------------------
__global__ void k_stats(const float* __restrict__ x){
    const int gi = blockIdx.x, ck = blockIdx.y, t = threadIdx.x;
    const float4* p = (const float4*)(x + (size_t)gi*524288 + (size_t)ck*65536);
    float s = 0.f, ss = 0.f;
    #pragma unroll 4
    for (int it = 0; it < 64; ++it){
        float4 v = p[it*256 + t];
        s  += v.x + v.y + v.z + v.w;
        ss += v.x*v.x + v.y*v.y + v.z*v.z + v.w*v.w;
    }
    #pragma unroll
    for (int d = 16; d; d >>= 1){
        s  += __shfl_xor_sync(0xffffffffu, s, d);
        ss += __shfl_xor_sync(0xffffffffu, ss, d);
    }
    __shared__ float sh[16];
    if ((t & 31) == 0){ sh[t>>5] = s; sh[8 + (t>>5)] = ss; }
    __syncthreads();
    if (t == 0){
        float S = 0.f, SS = 0.f;
        for (int i = 0; i < 8; ++i){ S += sh[i]; SS += sh[8+i]; }
        g_part[gi][ck][0] = S; g_part[gi][ck][1] = SS;
    }
}

__global__ void k_statfin(){
    const int t = threadIdx.x;
    float S = 0.f, SS = 0.f;
    for (int i = 0; i < 8; ++i){ S += g_part[t][i][0]; SS += g_part[t][i][1]; }
    const float inv = 1.f/524288.f;
    const float m = S*inv;
    const float v = SS*inv - m*m;
    g_mean[t] = m;
    g_rstd[t] = rsqrtf(v + 1e-5f);
}

// ---------------- fused GroupNorm-apply + QKV GEMM ---------------------------
// 256 threads / 8 warps, 2 CTAs/SM. CTA tile 128 tok x 128 m (6 M-iters),
// K in 2 chunks of 128. Warp tile 64 tok x 32 m. fp16 accumulate (full-rate
// HMMA) + double-buffered fragments. D = [tok][m] -> direct half2 stores.
__global__ __launch_bounds__(256, 2) void k_qkv(
    const float* __restrict__ x, const float* __restrict__ gamma,
    const float* __restrict__ beta, const float* __restrict__ bqkv)
{
    extern __shared__ __half sm[];
    __half* Bs = sm;               // [2 kc][128 tok][PCH]
    __half* As = sm + 2*CHUNK;     // [128 m][PCH]
    const int t  = threadIdx.x;
    const int bv = blockIdx.y;
    const int p0 = blockIdx.x * 128;
    const int lane = t & 31, warp = t >> 5;

    // ---- fill Bs: normalize x -> fp16, token-major rows, 2 K-chunks ----
    #pragma unroll
    for (int it = 0; it < 16; ++it){
        const int c = (it*8 + warp) * 2;
        const int gidx = bv*8 + (c >> 5);
        const float mu = g_mean[gidx], r = g_rstd[gidx];
        const float sc0 = r*gamma[c],   sh0 = beta[c]   - mu*sc0;
        const float sc1 = r*gamma[c+1], sh1 = beta[c+1] - mu*sc1;
        const float* x0 = x + ((size_t)(bv*256 + c))*HW + p0;
        const float* x1 = x0 + HW;
        __half* dst = Bs + (c >> 7)*CHUNK + (c & 127);
        #pragma unroll
        for (int i = 0; i < 4; ++i){
            const int j = i*32 + lane;
            *(__half2*)(dst + j*PCH) =
                __floats2half2_rn(x0[j]*sc0 + sh0, x1[j]*sc1 + sh1);
        }
    }
    loadA(As, g_wqkv, t);     // (mt=0, kc=0)
    __syncthreads();

    const int g = lane >> 2, tq = lane & 3;
    const int lrow  = lane & 15;
    const int khalf = lane >> 4;
    const int twarp = (warp >> 2) * 64;   // token offset (2 groups of 64)
    const int mwarp = (warp & 3) * 32;    // m offset     (4 groups of 32)

    uint32_t aB[4], bB[2];
    #pragma unroll
    for (int i = 0; i < 4; ++i)
        aB[i] = s2u(Bs + (twarp + i*16 + lrow)*PCH) + khalf*16;
    #pragma unroll
    for (int j = 0; j < 2; ++j)
        bB[j] = s2u(As + (mwarp + j*16 + lrow)*PCH) + khalf*16;

    #pragma unroll 1
    for (int mt = 0; mt < 6; ++mt){
        uint32_t acc[4][4][2];
        #pragma unroll
        for (int i=0;i<4;i++)
            #pragma unroll
            for (int j=0;j<4;j++){ acc[i][j][0]=0u; acc[i][j][1]=0u; }

        #pragma unroll 1
        for (int kc = 0; kc < 2; ++kc){
            const uint32_t boff = (uint32_t)kc * CHUNK_B;
            uint32_t ra[2][4][4], rb[2][2][4];
            #pragma unroll
            for (int i = 0; i < 4; ++i) ldsm4(ra[0][i], aB[i] + boff);
            #pragma unroll
            for (int j = 0; j < 2; ++j) ldsm4(rb[0][j], bB[j]);
            #pragma unroll
            for (int ks = 0; ks < 8; ++ks){
                const int cur = ks & 1, nxt = cur ^ 1;
                if (ks < 7){
                    #pragma unroll
                    for (int i = 0; i < 4; ++i) ldsm4(ra[nxt][i], aB[i] + boff + (ks+1)*32);
                    #pragma unroll
                    for (int j = 0; j < 2; ++j) ldsm4(rb[nxt][j], bB[j] + (ks+1)*32);
                }
                #pragma unroll
                for (int i = 0; i < 4; ++i)
                    #pragma unroll
                    for (int j = 0; j < 4; ++j)
                        mma_h(acc[i][j], ra[cur][i],
                              rb[cur][j>>1][j&1], rb[cur][j>>1][2 + (j&1)]);
            }
            __syncthreads();
            if (kc == 0){
                loadA(As, g_wqkv + (size_t)mt*128*256 + 128, t);
            } else if (mt < 5){
                loadA(As, g_wqkv + (size_t)(mt + 1)*128*256, t);
            }
            if (kc == 1){
                const float* bb = bqkv + mt*128 + mwarp;
                #pragma unroll
                for (int i = 0; i < 4; ++i){
                    const int tokA = p0 + twarp + i*16 + g;
                    __half* d0 = g_qkvT + ((size_t)(bv*HW + tokA))*768 + mt*128 + mwarp;
                    __half* d1 = d0 + (size_t)8*768;
                    #pragma unroll
                    for (int j = 0; j < 4; ++j){
                        const int m0 = j*8 + tq*2;
                        const __half2 b2 = __floats2half2_rn(bb[m0], bb[m0+1]);
                        *(__half2*)(d0 + m0) = __hadd2(*(__half2*)&acc[i][j][0], b2);
                        *(__half2*)(d1 + m0) = __hadd2(*(__half2*)&acc[i][j][1], b2);
                    }
                }
            }
            __syncthreads();
        }
    }
}

// ---------------- fused attention + proj GEMM + bias + residual ---------------
// CTA: one batch-pair x 64 pixels (128 tokens, view-major). 256 threads,
// 2 CTAs/SM. Phase 1: warp-per-pixel attention -> ao into Bs K-chunks.
// Phase 2: proj GEMM 128 tok x 256 ch (2 M-iters, 2 K-chunks), fp32 accum,
// warp tile 32ch x 64tok; fused bias + residual + direct float2 NCHW stores.
__global__ __launch_bounds__(256, 2) void k_proj(
    const float* __restrict__ x, const float* __restrict__ bproj, float* __restrict__ out)
{
    extern __shared__ __half sm[];
    __half* Bs = sm;               // [2 kc][128 tok][PCH] attention out
    __half* As = sm + 2*CHUNK;     // [128 ch][PCH] weights
    const int t  = threadIdx.x;
    const int b  = blockIdx.y;            // pair index
    const int p0 = blockIdx.x * 64;
    const int lane = t & 31, warp = t >> 5;

    // ---- phase 1: attention (8 pixels per warp) ----
    {
        const int off = (lane >> 3)*64 + (lane & 7)*8;   // channel offset 0..255
        const int chunk = off >> 7, cin = off & 127;
        #pragma unroll 2
        for (int itr = 0; itr < 8; ++itr){
            const int pix = warp*8 + itr;
            const __half* r0 = g_qkvT + ((size_t)(b*2*HW + p0 + pix))*768;
            const __half* r1 = r0 + (size_t)HW*768;
            float q0[8],q1[8],k0[8],k1[8],v0[8],v1[8];
            {
                uint4 u; const __half2* h = (const __half2*)&u; float2 f;
                #define LD8(dst, ptr) { u = *(const uint4*)(ptr); \
                    _Pragma("unroll") for (int e = 0; e < 4; ++e){ f = __half22float2(h[e]); dst[2*e]=f.x; dst[2*e+1]=f.y; } }
                LD8(q0, r0 + off);        LD8(q1, r1 + off);
                LD8(k0, r0 + 256 + off);  LD8(k1, r1 + 256 + off);
                LD8(v0, r0 + 512 + off);  LD8(v1, r1 + 512 + off);
                #undef LD8
            }
            float s00=0.f, s01=0.f, s10=0.f, s11=0.f;
            #pragma unroll
            for (int j = 0; j < 8; ++j){
                s00 += q0[j]*k0[j]; s01 += q0[j]*k1[j];
                s10 += q1[j]*k0[j]; s11 += q1[j]*k1[j];
            }
            #pragma unroll
            for (int d = 1; d < 8; d <<= 1){
                s00 += __shfl_xor_sync(0xffffffffu, s00, d);
                s01 += __shfl_xor_sync(0xffffffffu, s01, d);
                s10 += __shfl_xor_sync(0xffffffffu, s10, d);
                s11 += __shfl_xor_sync(0xffffffffu, s11, d);
            }
            const float sc = 0.125f;
            const float l00=s00*sc, l01=s01*sc, l10=s10*sc, l11=s11*sc;
            const float m0 = fmaxf(l00,l01), m1 = fmaxf(l10,l11);
            const float e00=__expf(l00-m0), e01=__expf(l01-m0);
            const float e10=__expf(l10-m1), e11=__expf(l11-m1);
            const float i0 = 1.f/(e00+e01), i1 = 1.f/(e10+e11);
            const float a00=e00*i0, a01=e01*i0, a10=e10*i1, a11=e11*i1;
            __align__(16) __half o0[8], o1[8];
            #pragma unroll
            for (int j = 0; j < 8; ++j){
                o0[j] = __float2half(a00*v0[j] + a01*v1[j]);
                o1[j] = __float2half(a10*v0[j] + a11*v1[j]);
            }
            *(uint4*)(Bs + chunk*CHUNK + pix*PCH + cin)        = *(const uint4*)o0;
            *(uint4*)(Bs + chunk*CHUNK + (64 + pix)*PCH + cin) = *(const uint4*)o1;
        }
    }
    loadA(As, g_wproj, t);    // (mt=0, kc=0)
    __syncthreads();

    // ---- phase 2: proj GEMM (fp32 accumulate) ----
    const int g = lane >> 2, tq = lane & 3;
    const int lrow  = lane & 15;
    const int khalf = lane >> 4;
    const int mwarp = (warp & 3) * 32;    // channel offset (4 groups of 32)
    const int twarp = (warp >> 2) * 64;   // token offset (view0/view1)
    const int view  = warp >> 2;

    uint32_t aB[2], bB[4];
    #pragma unroll
    for (int i = 0; i < 2; ++i)
        aB[i] = s2u(As + (mwarp + i*16 + lrow)*PCH) + khalf*16;
    #pragma unroll
    for (int j = 0; j < 4; ++j)
        bB[j] = s2u(Bs + (twarp + j*16 + lrow)*PCH) + khalf*16;

    #pragma unroll 1
    for (int mt = 0; mt < 2; ++mt){
        float acc[2][8][4];
        #pragma unroll
        for (int i=0;i<2;i++)
            #pragma unroll
            for (int j=0;j<8;j++)
                #pragma unroll
                for (int r=0;r<4;r++) acc[i][j][r]=0.f;

        #pragma unroll 1
        for (int kc = 0; kc < 2; ++kc){
            const uint32_t boff = (uint32_t)kc * CHUNK_B;
            #pragma unroll
            for (int ks = 0; ks < 8; ++ks){
                uint32_t ra[2][4], rb[4][4];
                #pragma unroll
                for (int i = 0; i < 2; ++i) ldsm4(ra[i], aB[i] + ks*32);
                #pragma unroll
                for (int j = 0; j < 4; ++j) ldsm4(rb[j], bB[j] + boff + ks*32);
                #pragma unroll
                for (int i = 0; i < 2; ++i)
                    #pragma unroll
                    for (int j = 0; j < 8; ++j)
                        mma_f(acc[i][j], ra[i],
                              rb[j>>1][j&1], rb[j>>1][2 + (j&1)]);
            }
            __syncthreads();
            if (kc == 0){
                loadA(As, g_wproj + (size_t)mt*128*256 + 128, t);
            } else if (mt == 0){
                loadA(As, g_wproj + (size_t)128*256, t);
            }
            if (kc == 1){
                #pragma unroll
                for (int i = 0; i < 2; ++i){
                    const int ch0 = mt*128 + mwarp + i*16 + g;
                    const int ch1 = ch0 + 8;
                    const float b0 = bproj[ch0], b1 = bproj[ch1];
                    const size_t base0 = ((size_t)((b*2 + view)*256 + ch0))*HW + p0;
                    const size_t base1 = ((size_t)((b*2 + view)*256 + ch1))*HW + p0;
                    #pragma unroll
                    for (int j = 0; j < 8; ++j){
                        const int tk = j*8 + tq*2;
                        float2 xv0 = *(const float2*)(x + base0 + tk);
                        float2 xv1 = *(const float2*)(x + base1 + tk);
                        *(float2*)(out + base0 + tk) =
                            make_float2(xv0.x + acc[i][j][0] + b0, xv0.y + acc[i][j][1] + b0);
                        *(float2*)(out + base1 + tk) =
                            make_float2(xv1.x + acc[i][j][2] + b1, xv1.y + acc[i][j][3] + b1);
                    }
                }
            }
            __syncthreads();
        }
    }
}

// ---------------- launch -------------------------------------------------------
extern "C" void kernel_launch(void* const* d_in, const int* in_sizes, int n_in,
                              void* d_out, int out_size)
{
    const float* x     = (const float*)d_in[0];
    const float* gam   = (const float*)d_in[1];
    const float* bet   = (const float*)d_in[2];
    const float* wqkv  = (const float*)d_in[3];
    const float* bqkv  = (const float*)d_in[4];
    const float* wproj = (const float*)d_in[5];
    const float* bproj = (const float*)d_in[6];
    float* out = (float*)d_out;

    cudaFuncSetAttribute(k_qkv,  cudaFuncAttributeMaxDynamicSharedMemorySize, FUSE_SMEM);
    cudaFuncSetAttribute(k_proj, cudaFuncAttributeMaxDynamicSharedMemorySize, FUSE_SMEM);

    k_convert<<<768, 256>>>(wqkv, wproj);
    k_stats<<<dim3(64, 8), 256>>>(x);
    k_statfin<<<1, 64>>>();
    k_qkv<<<dim3(128, 8), 256, FUSE_SMEM>>>(x, gam, bet, bqkv);
    k_proj<<<dim3(256, 4), 256, FUSE_SMEM>>>(x, bproj, out);
}